// round 5
// baseline (speedup 1.0000x reference)
#include <cuda_runtime.h>
#include <cuda_bf16.h>
#include <cooperative_groups.h>
#include <cstdint>

namespace cg = cooperative_groups;

// Problem constants
#define B_   64
#define C_   2048
#define HW_  192            // 24 * 8
#define HW4_ 48             // HW_/4 float4s per row
#define CSUB 16             // c-lanes per CTA
#define NTHR (CSUB * HW4_)  // 768 threads per CTA
#define CHALF (C_ / 2)      // 1024 channels per CTA (cluster of 2)
#define KITER (CHALF / CSUB) // 64 c-iterations per thread
#define NUM_IDS_ 751

// ---------------------------------------------------------------------------
// pid loader: pids buffer may be int32 (64 ints) or int64 (64 longs).
// Only the first 64 int32 words are read (256 B, safe under both layouts).
// int64 layout => odd words all 0 (values < 751); int32 => odd words random.
// ---------------------------------------------------------------------------
__device__ __forceinline__ int load_pid(const int* __restrict__ p32, int b)
{
    bool odd_all_zero = true;
    bool any_nonzero  = false;
    #pragma unroll
    for (int i = 0; i < 64; i += 2) {
        if (p32[i + 1] != 0) odd_all_zero = false;
        if (p32[i]     != 0) any_nonzero = true;
    }
    const bool is64 = odd_all_zero && any_nonzero;
    int pid = is64 ? p32[2 * b] : p32[b];
    if (pid < 0) pid = 0;
    if (pid >= NUM_IDS_) pid = NUM_IDS_ - 1;
    return pid;
}

// ---------------------------------------------------------------------------
// Fused kernel. Cluster of 2 CTAs per batch sample b.
//   CTA rank r owns channels [r*1024, (r+1)*1024).
//   Pass 1: half-heat reduction -> smem, DSMEM exchange, normalize (redundant)
//   Pass 2: scale own channel slice (re-read is L2-hot), write out.
// grid = 2*B_ = 128 CTAs, block = 768.
// ---------------------------------------------------------------------------
__global__ void __launch_bounds__(NTHR) __cluster_dims__(2, 1, 1)
fused_kernel(const float4* __restrict__ f4,
             const float*  __restrict__ w,
             const int*    __restrict__ pids32,
             float4*       __restrict__ out4)
{
    const int b    = blockIdx.x >> 1;
    const int half = blockIdx.x & 1;
    const int tid  = threadIdx.x;
    const int c_sub = tid / HW4_;   // 0..15
    const int q     = tid % HW4_;   // 0..47

    __shared__ float  ws[CHALF];          // weight slice (4 KB)
    __shared__ float4 sred[NTHR];         // c-lane partials (12 KB)
    __shared__ float  s_half[HW_];        // this CTA's half heat
    __shared__ float  s_heat[HW_];        // final normalized heat
    __shared__ float  smn[6], smx[6], s_bmn, s_bmx;
    __shared__ int    s_pid;

    if (tid == 0)
        s_pid = load_pid(pids32, b);
    __syncthreads();

    const int c0 = half * CHALF;
    {
        const float* wrow = w + (size_t)s_pid * C_ + c0;
        for (int i = tid; i < CHALF; i += NTHR)
            ws[i] = wrow[i];
    }
    __syncthreads();

    // ---------------- Pass 1: partial heat over own 1024 channels ----------
    // f4 index of (b, c, q) = (b*C + c)*HW4 + q
    const float4* fb = f4 + ((size_t)b * C_ + c0 + c_sub) * HW4_ + q;

    float4 acc = make_float4(0.f, 0.f, 0.f, 0.f);
    #pragma unroll 8
    for (int k = 0; k < KITER; k++) {
        const float4 v = fb[(size_t)k * CSUB * HW4_];
        const float  s = ws[c_sub + k * CSUB];
        acc.x = fmaf(s, v.x, acc.x);
        acc.y = fmaf(s, v.y, acc.y);
        acc.z = fmaf(s, v.z, acc.z);
        acc.w = fmaf(s, v.w, acc.w);
    }
    sred[tid] = acc;
    __syncthreads();

    // reduce 16 c-lanes -> half heat (threads 0..47, one float4 each)
    if (tid < HW4_) {
        float4 t = sred[tid];
        #pragma unroll
        for (int cs = 1; cs < CSUB; cs++) {
            const float4 u = sred[cs * HW4_ + tid];
            t.x += u.x; t.y += u.y; t.z += u.z; t.w += u.w;
        }
        s_half[tid * 4 + 0] = t.x;
        s_half[tid * 4 + 1] = t.y;
        s_half[tid * 4 + 2] = t.z;
        s_half[tid * 4 + 3] = t.w;
    }
    __syncthreads();

    // ---------------- DSMEM exchange of half heats -------------------------
    cg::cluster_group cluster = cg::this_cluster();
    cluster.sync();   // s_half visible cluster-wide

    const float* peer_half = cluster.map_shared_rank(s_half, half ^ 1);

    float sv = 0.f;
    if (tid < HW_)
        sv = s_half[tid] + peer_half[tid];

    cluster.sync();   // peer done reading our s_half before anyone proceeds

    // ---------------- min/max normalize (threads 0..191, 6 warps) ----------
    if (tid < HW_) {
        float mn = sv, mx = sv;
        #pragma unroll
        for (int off = 16; off > 0; off >>= 1) {
            mn = fminf(mn, __shfl_down_sync(0xffffffffu, mn, off));
            mx = fmaxf(mx, __shfl_down_sync(0xffffffffu, mx, off));
        }
        const int warp = tid >> 5, lane = tid & 31;
        if (lane == 0) { smn[warp] = mn; smx[warp] = mx; }
    }
    __syncthreads();
    if (tid == 0) {
        float m0 = smn[0], m1 = smx[0];
        #pragma unroll
        for (int i = 1; i < 6; i++) {
            m0 = fminf(m0, smn[i]);
            m1 = fmaxf(m1, smx[i]);
        }
        s_bmn = m0; s_bmx = m1;
    }
    __syncthreads();
    if (tid < HW_) {
        float h = sv;
        if (s_bmx != 0.f)
            h = (sv - s_bmn) / (s_bmx - s_bmn);
        s_heat[tid] = h;
    }
    __syncthreads();

    // ---------------- Pass 2: scale own channel slice ----------------------
    const float4 hv = *reinterpret_cast<const float4*>(&s_heat[q * 4]);
    const size_t base = ((size_t)b * C_ + c0 + c_sub) * HW4_ + q;

    #pragma unroll 8
    for (int k = 0; k < KITER; k++) {
        const size_t idx = base + (size_t)k * CSUB * HW4_;
        float4 v = f4[idx];
        v.x *= hv.x; v.y *= hv.y; v.z *= hv.z; v.w *= hv.w;
        out4[idx] = v;
    }
}

// ---------------------------------------------------------------------------
extern "C" void kernel_launch(void* const* d_in, const int* in_sizes, int n_in,
                              void* d_out, int out_size)
{
    // Resolve inputs by element count:
    //   features_map      : 25,165,824
    //   classifier_weight :  1,538,048
    //   pids              : 64
    const float* f = nullptr;
    const float* w = nullptr;
    const int*   p = nullptr;
    for (int i = 0; i < n_in; i++) {
        if      (in_sizes[i] == 25165824) f = (const float*)d_in[i];
        else if (in_sizes[i] == 1538048)  w = (const float*)d_in[i];
        else if (in_sizes[i] == 64)       p = (const int*)d_in[i];
    }
    float* out = (float*)d_out;

    fused_kernel<<<2 * B_, NTHR>>>((const float4*)f, w, p, (float4*)out);
}